// round 2
// baseline (speedup 1.0000x reference)
#include <cuda_runtime.h>

#define BATCH 8
#define HW 256
#define KK 13
#define HO 244   // 256 - 13 + 1

typedef unsigned long long ull;

// Scratch (allocation-free rule: __device__ globals)
static __device__ float g_h1[(size_t)BATCH * 64 * HW * HW];
static __device__ float g_h2[(size_t)BATCH * 64 * HW * HW];
static __device__ float g_w [(size_t)BATCH * 169 * HO * HO];

__device__ __forceinline__ ull mk2(float lo, float hi) {
    ull r; asm("mov.b64 %0,{%1,%2};" : "=l"(r) : "f"(lo), "f"(hi)); return r;
}
__device__ __forceinline__ void un2(ull p, float& lo, float& hi) {
    asm("mov.b64 {%0,%1},%2;" : "=f"(lo), "=f"(hi) : "l"(p));
}
__device__ __forceinline__ ull fma2(ull a, ull b, ull c) {
    ull d; asm("fma.rn.f32x2 %0,%1,%2,%3;" : "=l"(d) : "l"(a), "l"(b), "l"(c));
    return d;
}

// Direct 3x3 conv, packed-f32x2, register tiled.
// Block (16,8,2) = 256 threads. CTA tile: 64x16 pixels x 16 output channels
// (tz selects channel half, each thread does 8 channels x 2 rows x 4 cols).
template <int CIN, int CC, bool RELU>
__global__ void __launch_bounds__(256, 1) conv3x3_v2(
    const float* __restrict__ in, int inH, int inW,
    const float* __restrict__ Wt, const float* __restrict__ bias,
    float* __restrict__ out, int outH, int outW,
    int inOff, int OC, int ocGroups)
{
    __shared__ __align__(16) float  sIn[CC][18][66];
    __shared__ __align__(16) float2 sW2[16][CC][9];  // weights duplicated (w,w)

    const int tx = threadIdx.x, ty = threadIdx.y, tz = threadIdx.z;
    const int tid = tx + 16 * ty + 128 * tz;
    const int b  = blockIdx.z / ocGroups;
    const int og = blockIdx.z % ocGroups;
    const int ocBase = og * 16;
    const int x0 = blockIdx.x * 64, y0 = blockIdx.y * 16;

    ull acc[8][2][2];
#pragma unroll
    for (int o = 0; o < 8; ++o)
#pragma unroll
        for (int r = 0; r < 2; ++r)
#pragma unroll
            for (int p = 0; p < 2; ++p) acc[o][r][p] = 0ull;

    const float* inB = in + (size_t)b * CIN * inH * inW;

    for (int c0 = 0; c0 < CIN; c0 += CC) {
        // Stage input tile (halo, zero-padded / bounds-guarded)
        for (int idx = tid; idx < CC * 18 * 66; idx += 256) {
            int c  = idx / (18 * 66);
            int r  = idx % (18 * 66);
            int ry = r / 66, rx = r % 66;
            int iy = y0 + inOff + ry - 1;
            int ix = x0 + inOff + rx - 1;
            float v = 0.f;
            if (iy >= 0 && iy < inH && ix >= 0 && ix < inW)
                v = inB[((size_t)(c0 + c) * inH + iy) * inW + ix];
            sIn[c][ry][rx] = v;
        }
        // Stage weights as duplicated pairs (guard oc >= OC for padded groups)
        for (int idx = tid; idx < 16 * CC * 9; idx += 256) {
            int o = idx / (CC * 9);
            int r = idx % (CC * 9);
            int c = r / 9, t = r % 9;
            int oc = ocBase + o;
            float w = (oc < OC) ? Wt[((size_t)oc * CIN + (c0 + c)) * 9 + t] : 0.f;
            sW2[o][c][t] = make_float2(w, w);
        }
        __syncthreads();

#pragma unroll
        for (int c = 0; c < CC; ++c) {
            // Input row pairs: smem rows 2ty..2ty+3, float offsets 0..5 from 4tx.
            // rp[r][s] = pair starting at float offset s (s = 2p + kx).
            ull rp[4][5];
#pragma unroll
            for (int r = 0; r < 4; ++r) {
                const float* row = &sIn[c][2 * ty + r][4 * tx];
                ull A  = *(const ull*)(row);
                ull B  = *(const ull*)(row + 2);
                ull C2 = *(const ull*)(row + 4);
                float al, ah, bl, bh, cl, ch;
                un2(A, al, ah); un2(B, bl, bh); un2(C2, cl, ch);
                rp[r][0] = A;
                rp[r][1] = mk2(ah, bl);
                rp[r][2] = B;
                rp[r][3] = mk2(bh, cl);
                rp[r][4] = C2;
            }
#pragma unroll
            for (int o = 0; o < 8; ++o) {
#pragma unroll
                for (int ky = 0; ky < 3; ++ky) {
#pragma unroll
                    for (int kx = 0; kx < 3; ++kx) {
                        ull w2 = *(const ull*)&sW2[tz * 8 + o][c][ky * 3 + kx];
                        acc[o][0][0] = fma2(rp[ky][kx],         w2, acc[o][0][0]);
                        acc[o][0][1] = fma2(rp[ky][2 + kx],     w2, acc[o][0][1]);
                        acc[o][1][0] = fma2(rp[ky + 1][kx],     w2, acc[o][1][0]);
                        acc[o][1][1] = fma2(rp[ky + 1][2 + kx], w2, acc[o][1][1]);
                    }
                }
            }
        }
        __syncthreads();
    }

    // Epilogue: bias (+relu), float4 stores
    const int oxb = x0 + 4 * tx;
#pragma unroll
    for (int o = 0; o < 8; ++o) {
        int oc = ocBase + tz * 8 + o;
        if (oc >= OC) continue;
        float bv = bias[oc];
#pragma unroll
        for (int r = 0; r < 2; ++r) {
            int oy = y0 + 2 * ty + r;
            if (oy >= outH || oxb >= outW) continue;
            float v0, v1, v2, v3;
            un2(acc[o][r][0], v0, v1);
            un2(acc[o][r][1], v2, v3);
            v0 += bv; v1 += bv; v2 += bv; v3 += bv;
            if (RELU) {
                v0 = fmaxf(v0, 0.f); v1 = fmaxf(v1, 0.f);
                v2 = fmaxf(v2, 0.f); v3 = fmaxf(v3, 0.f);
            }
            *(float4*)&out[((size_t)((size_t)b * OC + oc) * outH + oy) * outW + oxb] =
                make_float4(v0, v1, v2, v3);
        }
    }
}

// y[b,i,j] = sum_{u,v} x[b, i+u, j+v] * w[b, u*13+v, i, j]
__global__ void __launch_bounds__(256) agg_kernel(
    const float* __restrict__ x, float* __restrict__ y)
{
    int id = blockIdx.x * 256 + threadIdx.x;
    if (id >= BATCH * HO * HO) return;
    int j = id % HO;
    int i = (id / HO) % HO;
    int b = id / (HO * HO);
    const float* xb = x + (size_t)b * HW * HW;
    const float* wb = g_w + (size_t)b * 169 * HO * HO + (size_t)i * HO + j;
    float acc = 0.f;
    for (int u = 0; u < KK; ++u) {
        const float* xr = xb + (size_t)(i + u) * HW + j;
#pragma unroll
        for (int v = 0; v < KK; ++v)
            acc = fmaf(xr[v], wb[(size_t)(u * KK + v) * HO * HO], acc);
    }
    y[id] = acc;
}

extern "C" void kernel_launch(void* const* d_in, const int* in_sizes, int n_in,
                              void* d_out, int out_size)
{
    const float* x  = (const float*)d_in[0];
    const float* W1 = (const float*)d_in[1];
    const float* b1 = (const float*)d_in[2];
    const float* W2 = (const float*)d_in[3];
    const float* b2 = (const float*)d_in[4];
    const float* W3 = (const float*)d_in[5];
    const float* b3 = (const float*)d_in[6];
    float* y = (float*)d_out;

    float *h1, *h2, *w;
    cudaGetSymbolAddress((void**)&h1, g_h1);
    cudaGetSymbolAddress((void**)&h2, g_h2);
    cudaGetSymbolAddress((void**)&w,  g_w);

    dim3 blk(16, 8, 2);

    // conv1: 1 -> 64, relu (4 channel-groups of 16)
    conv3x3_v2<1, 1, true><<<dim3(4, 16, BATCH * 4), blk>>>(
        x, HW, HW, W1, b1, h1, HW, HW, 0, 64, 4);

    // conv2: 64 -> 64, relu
    conv3x3_v2<64, 8, true><<<dim3(4, 16, BATCH * 4), blk>>>(
        h1, HW, HW, W2, b2, h2, HW, HW, 0, 64, 4);

    // conv3: 64 -> 169 (padded to 176), cropped interior only (244x244, +6)
    conv3x3_v2<64, 8, false><<<dim3(4, 16, BATCH * 11), blk>>>(
        h2, HW, HW, W3, b3, w, HO, HO, 6, 169, 11);

    // final per-pixel 13x13 patch dot-product
    int n = BATCH * HO * HO;
    agg_kernel<<<(n + 255) / 256, 256>>>(x, y);
}

// round 3
// speedup vs baseline: 1.1959x; 1.1959x over previous
#include <cuda_runtime.h>

#define BATCH 8
#define HW 256
#define KK 13
#define HO 244   // 256 - 13 + 1

// Scratch (allocation-free rule: __device__ globals)
static __device__ float g_h1[(size_t)BATCH * 64 * HW * HW];
static __device__ float g_h2[(size_t)BATCH * 64 * HW * HW];
static __device__ float g_w [(size_t)BATCH * 169 * HO * HO];

// Direct 3x3 conv, register-tiled: block (16,16), each thread computes a
// 2x2 output-pixel quad for 16 output channels (64 fp32 accumulators).
// CTA tile: 32x32 pixels x 16 oc. Input channels staged in chunks of CC.
// inOff shifts the input window (conv3 reads the interior at +6).
template <int CIN, int CC, bool RELU>
__global__ void __launch_bounds__(256) conv3x3_v3(
    const float* __restrict__ in, int inH, int inW,
    const float* __restrict__ Wt, const float* __restrict__ bias,
    float* __restrict__ out, int outH, int outW,
    int inOff, int OC, int ocGroups)
{
    __shared__ float sIn[CC][34][34];
    __shared__ float sW[16][CC][9];

    const int tx = threadIdx.x, ty = threadIdx.y;
    const int tid = ty * 16 + tx;
    const int b  = blockIdx.z / ocGroups;
    const int og = blockIdx.z % ocGroups;
    const int ocBase = og * 16;
    const int x0 = blockIdx.x * 32, y0 = blockIdx.y * 32;

    float acc[16][4];
#pragma unroll
    for (int o = 0; o < 16; ++o)
#pragma unroll
        for (int p = 0; p < 4; ++p) acc[o][p] = 0.f;

    const float* inB = in + (size_t)b * CIN * inH * inW;

    for (int c0 = 0; c0 < CIN; c0 += CC) {
        // Stage input tile (32x32 + halo), zero-padded / bounds-guarded
        for (int idx = tid; idx < CC * 34 * 34; idx += 256) {
            int c  = idx / (34 * 34);
            int r  = idx % (34 * 34);
            int ry = r / 34, rx = r % 34;
            int iy = y0 + inOff + ry - 1;
            int ix = x0 + inOff + rx - 1;
            float v = 0.f;
            if (iy >= 0 && iy < inH && ix >= 0 && ix < inW)
                v = inB[((size_t)(c0 + c) * inH + iy) * inW + ix];
            sIn[c][ry][rx] = v;
        }
        // Stage weight chunk (guard oc >= OC for padded last group)
        for (int idx = tid; idx < 16 * CC * 9; idx += 256) {
            int o = idx / (CC * 9);
            int r = idx % (CC * 9);
            int c = r / 9, t = r % 9;
            int oc = ocBase + o;
            sW[o][c][t] = (oc < OC)
                ? Wt[((size_t)oc * CIN + (c0 + c)) * 9 + t] : 0.f;
        }
        __syncthreads();

        // Keep the channel loop ROLLED (I$): body ~740 inst.
#pragma unroll 1
        for (int c = 0; c < CC; ++c) {
            // 4x4 input window for this thread's 2x2 quad
            float v[4][4];
#pragma unroll
            for (int u = 0; u < 4; ++u)
#pragma unroll
                for (int w = 0; w < 4; ++w)
                    v[u][w] = sIn[c][2 * ty + u][2 * tx + w];

#pragma unroll
            for (int o = 0; o < 16; ++o) {
#pragma unroll
                for (int ky = 0; ky < 3; ++ky) {
#pragma unroll
                    for (int kx = 0; kx < 3; ++kx) {
                        float wv = sW[o][c][ky * 3 + kx];
                        acc[o][0] = fmaf(v[ky    ][kx    ], wv, acc[o][0]);
                        acc[o][1] = fmaf(v[ky    ][kx + 1], wv, acc[o][1]);
                        acc[o][2] = fmaf(v[ky + 1][kx    ], wv, acc[o][2]);
                        acc[o][3] = fmaf(v[ky + 1][kx + 1], wv, acc[o][3]);
                    }
                }
            }
        }
        __syncthreads();
    }

    // Epilogue: bias (+relu), float2 stores. outW is even and quads start at
    // even x, so ox < outW implies ox+1 < outW.
    const int ox = x0 + 2 * tx;
#pragma unroll
    for (int o = 0; o < 16; ++o) {
        int oc = ocBase + o;
        if (oc >= OC) continue;
        float bv = bias[oc];
#pragma unroll
        for (int py = 0; py < 2; ++py) {
            int oy = y0 + 2 * ty + py;
            if (oy >= outH || ox >= outW) continue;
            float r0 = acc[o][2 * py    ] + bv;
            float r1 = acc[o][2 * py + 1] + bv;
            if (RELU) { r0 = fmaxf(r0, 0.f); r1 = fmaxf(r1, 0.f); }
            *(float2*)&out[((size_t)((size_t)b * OC + oc) * outH + oy) * outW + ox]
                = make_float2(r0, r1);
        }
    }
}

// y[b,i,j] = sum_{u,v} x[b, i+u, j+v] * w[b, u*13+v, i, j]
__global__ void __launch_bounds__(256) agg_kernel(
    const float* __restrict__ x, float* __restrict__ y)
{
    int id = blockIdx.x * 256 + threadIdx.x;
    if (id >= BATCH * HO * HO) return;
    int j = id % HO;
    int i = (id / HO) % HO;
    int b = id / (HO * HO);
    const float* xb = x + (size_t)b * HW * HW;
    const float* wb = g_w + (size_t)b * 169 * HO * HO + (size_t)i * HO + j;
    float acc = 0.f;
    for (int u = 0; u < KK; ++u) {
        const float* xr = xb + (size_t)(i + u) * HW + j;
#pragma unroll
        for (int v = 0; v < KK; ++v)
            acc = fmaf(xr[v], wb[(size_t)(u * KK + v) * HO * HO], acc);
    }
    y[id] = acc;
}

extern "C" void kernel_launch(void* const* d_in, const int* in_sizes, int n_in,
                              void* d_out, int out_size)
{
    const float* x  = (const float*)d_in[0];
    const float* W1 = (const float*)d_in[1];
    const float* b1 = (const float*)d_in[2];
    const float* W2 = (const float*)d_in[3];
    const float* b2 = (const float*)d_in[4];
    const float* W3 = (const float*)d_in[5];
    const float* b3 = (const float*)d_in[6];
    float* y = (float*)d_out;

    float *h1, *h2, *w;
    cudaGetSymbolAddress((void**)&h1, g_h1);
    cudaGetSymbolAddress((void**)&h2, g_h2);
    cudaGetSymbolAddress((void**)&w,  g_w);

    dim3 blk(16, 16);

    // conv1: 1 -> 64, relu (4 oc-groups of 16)
    conv3x3_v3<1, 1, true><<<dim3(8, 8, BATCH * 4), blk>>>(
        x, HW, HW, W1, b1, h1, HW, HW, 0, 64, 4);

    // conv2: 64 -> 64, relu
    conv3x3_v3<64, 8, true><<<dim3(8, 8, BATCH * 4), blk>>>(
        h1, HW, HW, W2, b2, h2, HW, HW, 0, 64, 4);

    // conv3: 64 -> 169 (padded to 176), cropped interior only (244x244, +6)
    conv3x3_v3<64, 8, false><<<dim3(8, 8, BATCH * 11), blk>>>(
        h2, HW, HW, W3, b3, w, HO, HO, 6, 169, 11);

    // final per-pixel 13x13 patch dot-product
    int n = BATCH * HO * HO;
    agg_kernel<<<(n + 255) / 256, 256>>>(x, y);
}

// round 4
// speedup vs baseline: 1.5762x; 1.3180x over previous
#include <cuda_runtime.h>

#define BATCH 8
#define HW 256
#define KK 13
#define HO 244   // 256 - 13 + 1

// ---- scratch (__device__ globals; no allocations allowed) ----
static __device__ float g_h1[(size_t)BATCH * 64 * HW * HW];    // conv1 out
static __device__ float g_h2[(size_t)BATCH * 64 * HW * HW];    // conv2 out
static __device__ float g_w [(size_t)BATCH * 169 * HO * HO];   // conv3 out (cropped)
static __device__ float g_U2[(size_t)16 * 64 * 64];            // transformed W2
static __device__ float g_U3[(size_t)16 * 169 * 64];           // transformed W3

// ---------------------------------------------------------------------------
// Weight transform: U = G g G^T for F(2x2,3x3). Layout U[xi][oc][cin].
__global__ void wino_wtrans(const float* __restrict__ Wt, float* __restrict__ U,
                            int OC, int CIN)
{
    int id = blockIdx.x * 256 + threadIdx.x;
    if (id >= OC * CIN) return;
    int oc = id / CIN, c = id % CIN;
    const float* g = Wt + (size_t)id * 9;
    float u[4][3];
#pragma unroll
    for (int j = 0; j < 3; ++j) {
        float g0 = g[j], g1 = g[3 + j], g2 = g[6 + j];
        u[0][j] = g0;
        u[1][j] = 0.5f * (g0 + g1 + g2);
        u[2][j] = 0.5f * (g0 - g1 + g2);
        u[3][j] = g2;
    }
#pragma unroll
    for (int i = 0; i < 4; ++i) {
        float a = u[i][0], b = u[i][1], cc = u[i][2];
        float U4[4] = { a, 0.5f * (a + b + cc), 0.5f * (a - b + cc), cc };
#pragma unroll
        for (int j = 0; j < 4; ++j)
            U[((size_t)(i * 4 + j) * OC + oc) * CIN + c] = U4[j];
    }
}

// ---------------------------------------------------------------------------
// Winograd F(2x2,3x3) conv, CIN=64, CC=8 channel chunks.
// CTA: 16x16 outputs (8x8 tiles) x 16 output channels.
// Threads 256: xi = tid&15, ocg = (tid>>4)&1 (8 oc), tg = tid>>5 (8 tiles).
// Dynamic smem: sIn[8][18][18] | sV[8][64][17] | sU[16][137] | sM[8][64][17]
#define SMEM_FLOATS (2592 + 8704 + 2192 + 8704)

template <bool RELU>
__global__ void __launch_bounds__(256, 2) wino_conv(
    const float* __restrict__ in,
    const float* __restrict__ Ug, const float* __restrict__ bias,
    float* __restrict__ out, int outH, int outW,
    int inOff, int OC, int ocGroups)
{
    extern __shared__ float sm[];
    float* sIn = sm;            // 8*18*18
    float* sV  = sm + 2592;     // (c*64+tile)*17 + xi
    float* sU  = sm + 11296;    // xi*137 + c*17 + oc
    float* sM  = sm + 13488;    // (oc*64+tile)*17 + xi

    const int tid = threadIdx.x;
    const int xi  = tid & 15;
    const int ocg = (tid >> 4) & 1;
    const int tg  = tid >> 5;

    const int b  = blockIdx.z / ocGroups;
    const int og = blockIdx.z % ocGroups;
    const int ocBase = og * 16;
    const int x0 = blockIdx.x * 16, y0 = blockIdx.y * 16;

    const float* inB = in + (size_t)b * 64 * HW * HW;

    float acc[8][8];
#pragma unroll
    for (int j = 0; j < 8; ++j)
#pragma unroll
        for (int t = 0; t < 8; ++t) acc[j][t] = 0.f;

    for (int c0 = 0; c0 < 64; c0 += 8) {
        // ---- stage input chunk (18x18 with halo, guarded) ----
        for (int idx = tid; idx < 8 * 18 * 18; idx += 256) {
            int c  = idx / 324;
            int r  = idx % 324;
            int ry = r / 18, rx = r % 18;
            int iy = y0 + inOff + ry - 1;
            int ix = x0 + inOff + rx - 1;
            float v = 0.f;
            if (iy >= 0 && iy < HW && ix >= 0 && ix < HW)
                v = inB[((size_t)(c0 + c) * HW + iy) * HW + ix];
            sIn[idx] = v;
        }
        __syncthreads();

        // ---- phase A: input transform V = B^T d B ; also stage U chunk ----
        for (int p = tid; p < 512; p += 256) {
            int c = p >> 6, t = p & 63;
            int ty = t >> 3, tx = t & 7;
            const float* base = sIn + c * 324 + (ty * 2) * 18 + tx * 2;
            float d[4][4];
#pragma unroll
            for (int r = 0; r < 4; ++r)
#pragma unroll
                for (int s = 0; s < 4; ++s) d[r][s] = base[r * 18 + s];
            float z[4][4];
#pragma unroll
            for (int s = 0; s < 4; ++s) {
                z[0][s] = d[0][s] - d[2][s];
                z[1][s] = d[1][s] + d[2][s];
                z[2][s] = d[2][s] - d[1][s];
                z[3][s] = d[1][s] - d[3][s];
            }
            float* dst = sV + (c * 64 + t) * 17;
#pragma unroll
            for (int i = 0; i < 4; ++i) {
                dst[i * 4 + 0] = z[i][0] - z[i][2];
                dst[i * 4 + 1] = z[i][1] + z[i][2];
                dst[i * 4 + 2] = z[i][2] - z[i][1];
                dst[i * 4 + 3] = z[i][1] - z[i][3];
            }
        }
        for (int idx = tid; idx < 2048; idx += 256) {
            int x  = idx >> 7;
            int r  = idx & 127;
            int c  = r >> 4, oc = r & 15;
            int ocG = ocBase + oc;
            float u = (ocG < OC)
                ? Ug[((size_t)x * OC + ocG) * 64 + c0 + c] : 0.f;
            sU[x * 137 + c * 17 + oc] = u;
        }
        __syncthreads();

        // ---- phase B: M[oc][tile] += U[xi][oc][c] * V[xi][c][tile] ----
#pragma unroll
        for (int c = 0; c < 8; ++c) {
            float vv[8], uu[8];
#pragma unroll
            for (int t = 0; t < 8; ++t)
                vv[t] = sV[(c * 64 + tg * 8 + t) * 17 + xi];
#pragma unroll
            for (int j = 0; j < 8; ++j)
                uu[j] = sU[xi * 137 + c * 17 + ocg * 8 + j];
#pragma unroll
            for (int j = 0; j < 8; ++j)
#pragma unroll
                for (int t = 0; t < 8; ++t)
                    acc[j][t] = fmaf(uu[j], vv[t], acc[j][t]);
        }
        __syncthreads();
    }

    // ---- phase C: output transform Y = A^T M A, in two oc halves ----
#pragma unroll 1
    for (int h = 0; h < 2; ++h) {
        if (ocg == h) {
#pragma unroll
            for (int j = 0; j < 8; ++j)
#pragma unroll
                for (int t = 0; t < 8; ++t)
                    sM[(j * 64 + tg * 8 + t) * 17 + xi] = acc[j][t];
        }
        __syncthreads();
        for (int p = tid; p < 512; p += 256) {
            int oc = p >> 6, t = p & 63;
            int ocG = ocBase + h * 8 + oc;
            if (ocG < OC) {
                const float* src = sM + (oc * 64 + t) * 17;
                float m[4][4];
#pragma unroll
                for (int i = 0; i < 4; ++i)
#pragma unroll
                    for (int j = 0; j < 4; ++j) m[i][j] = src[i * 4 + j];
                float s0[4], s1[4];
#pragma unroll
                for (int j = 0; j < 4; ++j) {
                    s0[j] = m[0][j] + m[1][j] + m[2][j];
                    s1[j] = m[1][j] - m[2][j] - m[3][j];
                }
                float bv = bias[ocG];
                float y00 = s0[0] + s0[1] + s0[2] + bv;
                float y01 = s0[1] - s0[2] - s0[3] + bv;
                float y10 = s1[0] + s1[1] + s1[2] + bv;
                float y11 = s1[1] - s1[2] - s1[3] + bv;
                if (RELU) {
                    y00 = fmaxf(y00, 0.f); y01 = fmaxf(y01, 0.f);
                    y10 = fmaxf(y10, 0.f); y11 = fmaxf(y11, 0.f);
                }
                int oy = y0 + (t >> 3) * 2;
                int ox = x0 + (t & 7) * 2;
                float* o0 = out + ((size_t)((size_t)blockIdx.z / ocGroups * OC + ocG)
                                   * outH + oy) * outW + ox;
                if (oy < outH) {
                    if (ox     < outW) o0[0] = y00;
                    if (ox + 1 < outW) o0[1] = y01;
                }
                if (oy + 1 < outH) {
                    if (ox     < outW) o0[outW]     = y10;
                    if (ox + 1 < outW) o0[outW + 1] = y11;
                }
            }
        }
        __syncthreads();
    }
}

// ---------------------------------------------------------------------------
// conv1 (1 -> 64): direct, register-tiled (cheap layer).
template <int CIN, int CC, bool RELU>
__global__ void __launch_bounds__(256) conv3x3_v3(
    const float* __restrict__ in, int inH, int inW,
    const float* __restrict__ Wt, const float* __restrict__ bias,
    float* __restrict__ out, int outH, int outW,
    int inOff, int OC, int ocGroups)
{
    __shared__ float sIn[CC][34][34];
    __shared__ float sW[16][CC][9];

    const int tx = threadIdx.x, ty = threadIdx.y;
    const int tid = ty * 16 + tx;
    const int b  = blockIdx.z / ocGroups;
    const int og = blockIdx.z % ocGroups;
    const int ocBase = og * 16;
    const int x0 = blockIdx.x * 32, y0 = blockIdx.y * 32;

    float acc[16][4];
#pragma unroll
    for (int o = 0; o < 16; ++o)
#pragma unroll
        for (int p = 0; p < 4; ++p) acc[o][p] = 0.f;

    const float* inB = in + (size_t)b * CIN * inH * inW;

    for (int c0 = 0; c0 < CIN; c0 += CC) {
        for (int idx = tid; idx < CC * 34 * 34; idx += 256) {
            int c  = idx / (34 * 34);
            int r  = idx % (34 * 34);
            int ry = r / 34, rx = r % 34;
            int iy = y0 + inOff + ry - 1;
            int ix = x0 + inOff + rx - 1;
            float v = 0.f;
            if (iy >= 0 && iy < inH && ix >= 0 && ix < inW)
                v = inB[((size_t)(c0 + c) * inH + iy) * inW + ix];
            sIn[c][ry][rx] = v;
        }
        for (int idx = tid; idx < 16 * CC * 9; idx += 256) {
            int o = idx / (CC * 9);
            int r = idx % (CC * 9);
            int c = r / 9, t = r % 9;
            int oc = ocBase + o;
            sW[o][c][t] = (oc < OC)
                ? Wt[((size_t)oc * CIN + (c0 + c)) * 9 + t] : 0.f;
        }
        __syncthreads();

#pragma unroll 1
        for (int c = 0; c < CC; ++c) {
            float v[4][4];
#pragma unroll
            for (int u = 0; u < 4; ++u)
#pragma unroll
                for (int w = 0; w < 4; ++w)
                    v[u][w] = sIn[c][2 * ty + u][2 * tx + w];
#pragma unroll
            for (int o = 0; o < 16; ++o) {
#pragma unroll
                for (int ky = 0; ky < 3; ++ky) {
#pragma unroll
                    for (int kx = 0; kx < 3; ++kx) {
                        float wv = sW[o][c][ky * 3 + kx];
                        acc[o][0] = fmaf(v[ky    ][kx    ], wv, acc[o][0]);
                        acc[o][1] = fmaf(v[ky    ][kx + 1], wv, acc[o][1]);
                        acc[o][2] = fmaf(v[ky + 1][kx    ], wv, acc[o][2]);
                        acc[o][3] = fmaf(v[ky + 1][kx + 1], wv, acc[o][3]);
                    }
                }
            }
        }
        __syncthreads();
    }

    const int ox = x0 + 2 * tx;
#pragma unroll
    for (int o = 0; o < 16; ++o) {
        int oc = ocBase + o;
        if (oc >= OC) continue;
        float bv = bias[oc];
#pragma unroll
        for (int py = 0; py < 2; ++py) {
            int oy = y0 + 2 * ty + py;
            if (oy >= outH || ox >= outW) continue;
            float r0 = acc[o][2 * py    ] + bv;
            float r1 = acc[o][2 * py + 1] + bv;
            if (RELU) { r0 = fmaxf(r0, 0.f); r1 = fmaxf(r1, 0.f); }
            *(float2*)&out[((size_t)((size_t)b * OC + oc) * outH + oy) * outW + ox]
                = make_float2(r0, r1);
        }
    }
}

// y[b,i,j] = sum_{u,v} x[b, i+u, j+v] * w[b, u*13+v, i, j]
__global__ void __launch_bounds__(256) agg_kernel(
    const float* __restrict__ x, float* __restrict__ y)
{
    int id = blockIdx.x * 256 + threadIdx.x;
    if (id >= BATCH * HO * HO) return;
    int j = id % HO;
    int i = (id / HO) % HO;
    int b = id / (HO * HO);
    const float* xb = x + (size_t)b * HW * HW;
    const float* wb = g_w + (size_t)b * 169 * HO * HO + (size_t)i * HO + j;
    float acc = 0.f;
    for (int u = 0; u < KK; ++u) {
        const float* xr = xb + (size_t)(i + u) * HW + j;
#pragma unroll
        for (int v = 0; v < KK; ++v)
            acc = fmaf(xr[v], wb[(size_t)(u * KK + v) * HO * HO], acc);
    }
    y[id] = acc;
}

extern "C" void kernel_launch(void* const* d_in, const int* in_sizes, int n_in,
                              void* d_out, int out_size)
{
    const float* x  = (const float*)d_in[0];
    const float* W1 = (const float*)d_in[1];
    const float* b1 = (const float*)d_in[2];
    const float* W2 = (const float*)d_in[3];
    const float* b2 = (const float*)d_in[4];
    const float* W3 = (const float*)d_in[5];
    const float* b3 = (const float*)d_in[6];
    float* y = (float*)d_out;

    float *h1, *h2, *w, *U2, *U3;
    cudaGetSymbolAddress((void**)&h1, g_h1);
    cudaGetSymbolAddress((void**)&h2, g_h2);
    cudaGetSymbolAddress((void**)&w,  g_w);
    cudaGetSymbolAddress((void**)&U2, g_U2);
    cudaGetSymbolAddress((void**)&U3, g_U3);

    static int inited = 0;
    if (!inited) {
        cudaFuncSetAttribute(wino_conv<true>,
            cudaFuncAttributeMaxDynamicSharedMemorySize, SMEM_FLOATS * 4);
        cudaFuncSetAttribute(wino_conv<false>,
            cudaFuncAttributeMaxDynamicSharedMemorySize, SMEM_FLOATS * 4);
        inited = 1;
    }

    // weight transforms (tiny)
    wino_wtrans<<<(64 * 64 + 255) / 256, 256>>>(W2, U2, 64, 64);
    wino_wtrans<<<(169 * 64 + 255) / 256, 256>>>(W3, U3, 169, 64);

    // conv1: 1 -> 64, relu (direct)
    conv3x3_v3<1, 1, true><<<dim3(8, 8, BATCH * 4), dim3(16, 16)>>>(
        x, HW, HW, W1, b1, h1, HW, HW, 0, 64, 4);

    // conv2: 64 -> 64, relu (Winograd)
    wino_conv<true><<<dim3(16, 16, BATCH * 4), 256, SMEM_FLOATS * 4>>>(
        h1, U2, b2, h2, HW, HW, 0, 64, 4);

    // conv3: 64 -> 169 (pad to 176), cropped interior (244x244, +6), no relu
    wino_conv<false><<<dim3(16, 16, BATCH * 11), 256, SMEM_FLOATS * 4>>>(
        h2, U3, b3, w, HO, HO, 6, 169, 11);

    // final per-pixel 13x13 patch dot-product
    int n = BATCH * HO * HO;
    agg_kernel<<<(n + 255) / 256, 256>>>(x, y);
}

// round 5
// speedup vs baseline: 1.9918x; 1.2637x over previous
#include <cuda_runtime.h>

#define BATCH 8
#define HW 256
#define KK 13
#define HO 244   // 256 - 13 + 1

// ---- scratch (__device__ globals; no allocations allowed) ----
static __device__ float g_h1[(size_t)BATCH * 64 * HW * HW];    // conv1 out
static __device__ float g_h2[(size_t)BATCH * 64 * HW * HW];    // conv2 out
static __device__ float g_w [(size_t)BATCH * 169 * HO * HO];   // conv3 out (cropped)
static __device__ float g_U2[(size_t)16 * 64 * 64];            // W2: [xi][cin][oc]
static __device__ float g_U3[(size_t)16 * 64 * 169];           // W3: [xi][cin][oc]

// ---------------------------------------------------------------------------
// Weight transform: U = G g G^T for F(2x2,3x3). Gmem layout U[xi][cin][oc]
// (oc contiguous -> coalesced staging loads in wino_conv).
__global__ void wino_wtrans(const float* __restrict__ Wt, float* __restrict__ U,
                            int OC, int CIN)
{
    int id = blockIdx.x * 256 + threadIdx.x;
    if (id >= OC * CIN) return;
    int oc = id / CIN, c = id % CIN;
    const float* g = Wt + (size_t)id * 9;
    float u[4][3];
#pragma unroll
    for (int j = 0; j < 3; ++j) {
        float g0 = g[j], g1 = g[3 + j], g2 = g[6 + j];
        u[0][j] = g0;
        u[1][j] = 0.5f * (g0 + g1 + g2);
        u[2][j] = 0.5f * (g0 - g1 + g2);
        u[3][j] = g2;
    }
#pragma unroll
    for (int i = 0; i < 4; ++i) {
        float a = u[i][0], b = u[i][1], cc = u[i][2];
        float U4[4] = { a, 0.5f * (a + b + cc), 0.5f * (a - b + cc), cc };
#pragma unroll
        for (int j = 0; j < 4; ++j)
            U[((size_t)(i * 4 + j) * CIN + c) * OC + oc] = U4[j];
    }
}

// ---------------------------------------------------------------------------
// Winograd F(2x2,3x3) conv, CIN=64 in chunks of 8.
// CTA: 16x16 outputs (8x8 tiles) x 16 output channels.
// Threads 256: xi = tid&15, ocg = (tid>>4)&1 (8 oc), tg = tid>>5 (8 tiles).
// smem (floats): sIn[0,2592) | sU[2592,5152) c*16+xi stride 20 |
//                sV[5152,13856) c*16+xi stride 68 | sM aliases sV
#define SMEM_FLOATS 13856

template <bool RELU>
__global__ void __launch_bounds__(256, 2) wino_conv(
    const float* __restrict__ in,
    const float* __restrict__ Ug, const float* __restrict__ bias,
    float* __restrict__ out, int outH, int outW,
    int inOff, int OC, int ocGroups)
{
    extern __shared__ float sm[];
    float* sIn = sm;            // 8*18*18
    float* sU  = sm + 2592;     // (c*16 + xi)*20 + oc      (8*16*20 = 2560)
    float* sV  = sm + 5152;     // (c*16 + xi)*68 + tile    (8*16*68 = 8704)
    float* sM  = sm + 5152;     // phase C: (oc*64 + tile)*17 + xi  (aliases sV)

    const int tid = threadIdx.x;
    const int xi  = tid & 15;
    const int ocg = (tid >> 4) & 1;
    const int tg  = tid >> 5;

    const int b  = blockIdx.z / ocGroups;
    const int og = blockIdx.z % ocGroups;
    const int ocBase = og * 16;
    const int x0 = blockIdx.x * 16, y0 = blockIdx.y * 16;

    const float* inB = in + (size_t)b * 64 * HW * HW;

    float acc[8][8];
#pragma unroll
    for (int j = 0; j < 8; ++j)
#pragma unroll
        for (int t = 0; t < 8; ++t) acc[j][t] = 0.f;

    for (int c0 = 0; c0 < 64; c0 += 8) {
        // ---- stage input chunk (18x18 with halo, guarded) ----
        for (int idx = tid; idx < 8 * 18 * 18; idx += 256) {
            int c  = idx / 324;
            int r  = idx % 324;
            int ry = r / 18, rx = r % 18;
            int iy = y0 + inOff + ry - 1;
            int ix = x0 + inOff + rx - 1;
            float v = 0.f;
            if (iy >= 0 && iy < HW && ix >= 0 && ix < HW)
                v = inB[((size_t)(c0 + c) * HW + iy) * HW + ix];
            sIn[idx] = v;
        }
        // ---- stage U chunk: gmem [xi][cin][oc] -> sU[c][xi][oc] ----
        for (int idx = tid; idx < 2048; idx += 256) {
            int x  = idx >> 7;          // xi
            int r  = idx & 127;
            int c  = r >> 4, oc = r & 15;
            int ocG = ocBase + oc;
            float u = (ocG < OC)
                ? Ug[((size_t)x * 64 + c0 + c) * OC + ocG] : 0.f;
            sU[(c * 16 + x) * 20 + oc] = u;
        }
        __syncthreads();

        // ---- phase A: input transform V = B^T d B -> sV[c][xi][tile] ----
        for (int p = tid; p < 512; p += 256) {
            int c = p >> 6, t = p & 63;
            int ty = t >> 3, tx = t & 7;
            const float* base = sIn + c * 324 + (ty * 2) * 18 + tx * 2;
            float d[4][4];
#pragma unroll
            for (int r = 0; r < 4; ++r)
#pragma unroll
                for (int s = 0; s < 4; ++s) d[r][s] = base[r * 18 + s];
            float z[4][4];
#pragma unroll
            for (int s = 0; s < 4; ++s) {
                z[0][s] = d[0][s] - d[2][s];
                z[1][s] = d[1][s] + d[2][s];
                z[2][s] = d[2][s] - d[1][s];
                z[3][s] = d[1][s] - d[3][s];
            }
#pragma unroll
            for (int i = 0; i < 4; ++i) {
                float w0 = z[i][0] - z[i][2];
                float w1 = z[i][1] + z[i][2];
                float w2 = z[i][2] - z[i][1];
                float w3 = z[i][1] - z[i][3];
                sV[(c * 16 + i * 4 + 0) * 68 + t] = w0;
                sV[(c * 16 + i * 4 + 1) * 68 + t] = w1;
                sV[(c * 16 + i * 4 + 2) * 68 + t] = w2;
                sV[(c * 16 + i * 4 + 3) * 68 + t] = w3;
            }
        }
        __syncthreads();

        // ---- phase B: vectorized rank-1 updates per channel ----
#pragma unroll
        for (int c = 0; c < 8; ++c) {
            const float4 v0 = *(const float4*)&sV[(c * 16 + xi) * 68 + tg * 8];
            const float4 v1 = *(const float4*)&sV[(c * 16 + xi) * 68 + tg * 8 + 4];
            const float4 u0 = *(const float4*)&sU[(c * 16 + xi) * 20 + ocg * 8];
            const float4 u1 = *(const float4*)&sU[(c * 16 + xi) * 20 + ocg * 8 + 4];
            float vv[8] = { v0.x, v0.y, v0.z, v0.w, v1.x, v1.y, v1.z, v1.w };
            float uu[8] = { u0.x, u0.y, u0.z, u0.w, u1.x, u1.y, u1.z, u1.w };
#pragma unroll
            for (int j = 0; j < 8; ++j)
#pragma unroll
                for (int t = 0; t < 8; ++t)
                    acc[j][t] = fmaf(uu[j], vv[t], acc[j][t]);
        }
        __syncthreads();
    }

    // ---- phase C: output transform Y = A^T M A, two oc halves via sM ----
#pragma unroll 1
    for (int h = 0; h < 2; ++h) {
        if (ocg == h) {
#pragma unroll
            for (int j = 0; j < 8; ++j)
#pragma unroll
                for (int t = 0; t < 8; ++t)
                    sM[(j * 64 + tg * 8 + t) * 17 + xi] = acc[j][t];
        }
        __syncthreads();
        for (int p = tid; p < 512; p += 256) {
            int oc = p >> 6, t = p & 63;
            int ocG = ocBase + h * 8 + oc;
            if (ocG < OC) {
                const float* src = sM + (oc * 64 + t) * 17;
                float m[4][4];
#pragma unroll
                for (int i = 0; i < 4; ++i)
#pragma unroll
                    for (int j = 0; j < 4; ++j) m[i][j] = src[i * 4 + j];
                float s0[4], s1[4];
#pragma unroll
                for (int j = 0; j < 4; ++j) {
                    s0[j] = m[0][j] + m[1][j] + m[2][j];
                    s1[j] = m[1][j] - m[2][j] - m[3][j];
                }
                float bv = bias[ocG];
                float y00 = s0[0] + s0[1] + s0[2] + bv;
                float y01 = s0[1] - s0[2] - s0[3] + bv;
                float y10 = s1[0] + s1[1] + s1[2] + bv;
                float y11 = s1[1] - s1[2] - s1[3] + bv;
                if (RELU) {
                    y00 = fmaxf(y00, 0.f); y01 = fmaxf(y01, 0.f);
                    y10 = fmaxf(y10, 0.f); y11 = fmaxf(y11, 0.f);
                }
                int oy = y0 + (t >> 3) * 2;
                int ox = x0 + (t & 7) * 2;
                float* o0 = out + ((size_t)((size_t)b * OC + ocG)
                                   * outH + oy) * outW + ox;
                if (oy < outH) {
                    if (ox     < outW) o0[0] = y00;
                    if (ox + 1 < outW) o0[1] = y01;
                }
                if (oy + 1 < outH) {
                    if (ox     < outW) o0[outW]     = y10;
                    if (ox + 1 < outW) o0[outW + 1] = y11;
                }
            }
        }
        __syncthreads();
    }
}

// ---------------------------------------------------------------------------
// conv1 (1 -> 64): direct, register-tiled (cheap layer).
template <int CIN, int CC, bool RELU>
__global__ void __launch_bounds__(256) conv3x3_v3(
    const float* __restrict__ in, int inH, int inW,
    const float* __restrict__ Wt, const float* __restrict__ bias,
    float* __restrict__ out, int outH, int outW,
    int inOff, int OC, int ocGroups)
{
    __shared__ float sIn[CC][34][34];
    __shared__ float sW[16][CC][9];

    const int tx = threadIdx.x, ty = threadIdx.y;
    const int tid = ty * 16 + tx;
    const int b  = blockIdx.z / ocGroups;
    const int og = blockIdx.z % ocGroups;
    const int ocBase = og * 16;
    const int x0 = blockIdx.x * 32, y0 = blockIdx.y * 32;

    float acc[16][4];
#pragma unroll
    for (int o = 0; o < 16; ++o)
#pragma unroll
        for (int p = 0; p < 4; ++p) acc[o][p] = 0.f;

    const float* inB = in + (size_t)b * CIN * inH * inW;

    for (int c0 = 0; c0 < CIN; c0 += CC) {
        for (int idx = tid; idx < CC * 34 * 34; idx += 256) {
            int c  = idx / (34 * 34);
            int r  = idx % (34 * 34);
            int ry = r / 34, rx = r % 34;
            int iy = y0 + inOff + ry - 1;
            int ix = x0 + inOff + rx - 1;
            float v = 0.f;
            if (iy >= 0 && iy < inH && ix >= 0 && ix < inW)
                v = inB[((size_t)(c0 + c) * inH + iy) * inW + ix];
            sIn[c][ry][rx] = v;
        }
        for (int idx = tid; idx < 16 * CC * 9; idx += 256) {
            int o = idx / (CC * 9);
            int r = idx % (CC * 9);
            int c = r / 9, t = r % 9;
            int oc = ocBase + o;
            sW[o][c][t] = (oc < OC)
                ? Wt[((size_t)oc * CIN + (c0 + c)) * 9 + t] : 0.f;
        }
        __syncthreads();

#pragma unroll 1
        for (int c = 0; c < CC; ++c) {
            float v[4][4];
#pragma unroll
            for (int u = 0; u < 4; ++u)
#pragma unroll
                for (int w = 0; w < 4; ++w)
                    v[u][w] = sIn[c][2 * ty + u][2 * tx + w];
#pragma unroll
            for (int o = 0; o < 16; ++o) {
#pragma unroll
                for (int ky = 0; ky < 3; ++ky) {
#pragma unroll
                    for (int kx = 0; kx < 3; ++kx) {
                        float wv = sW[o][c][ky * 3 + kx];
                        acc[o][0] = fmaf(v[ky    ][kx    ], wv, acc[o][0]);
                        acc[o][1] = fmaf(v[ky    ][kx + 1], wv, acc[o][1]);
                        acc[o][2] = fmaf(v[ky + 1][kx    ], wv, acc[o][2]);
                        acc[o][3] = fmaf(v[ky + 1][kx + 1], wv, acc[o][3]);
                    }
                }
            }
        }
        __syncthreads();
    }

    const int ox = x0 + 2 * tx;
#pragma unroll
    for (int o = 0; o < 16; ++o) {
        int oc = ocBase + o;
        if (oc >= OC) continue;
        float bv = bias[oc];
#pragma unroll
        for (int py = 0; py < 2; ++py) {
            int oy = y0 + 2 * ty + py;
            if (oy >= outH || ox >= outW) continue;
            float r0 = acc[o][2 * py    ] + bv;
            float r1 = acc[o][2 * py + 1] + bv;
            if (RELU) { r0 = fmaxf(r0, 0.f); r1 = fmaxf(r1, 0.f); }
            *(float2*)&out[((size_t)((size_t)b * OC + oc) * outH + oy) * outW + ox]
                = make_float2(r0, r1);
        }
    }
}

// y[b,i,j] = sum_{u,v} x[b, i+u, j+v] * w[b, u*13+v, i, j]
__global__ void __launch_bounds__(256) agg_kernel(
    const float* __restrict__ x, float* __restrict__ y)
{
    int id = blockIdx.x * 256 + threadIdx.x;
    if (id >= BATCH * HO * HO) return;
    int j = id % HO;
    int i = (id / HO) % HO;
    int b = id / (HO * HO);
    const float* xb = x + (size_t)b * HW * HW;
    const float* wb = g_w + (size_t)b * 169 * HO * HO + (size_t)i * HO + j;
    float acc = 0.f;
    for (int u = 0; u < KK; ++u) {
        const float* xr = xb + (size_t)(i + u) * HW + j;
#pragma unroll
        for (int v = 0; v < KK; ++v)
            acc = fmaf(xr[v], wb[(size_t)(u * KK + v) * HO * HO], acc);
    }
    y[id] = acc;
}

extern "C" void kernel_launch(void* const* d_in, const int* in_sizes, int n_in,
                              void* d_out, int out_size)
{
    const float* x  = (const float*)d_in[0];
    const float* W1 = (const float*)d_in[1];
    const float* b1 = (const float*)d_in[2];
    const float* W2 = (const float*)d_in[3];
    const float* b2 = (const float*)d_in[4];
    const float* W3 = (const float*)d_in[5];
    const float* b3 = (const float*)d_in[6];
    float* y = (float*)d_out;

    float *h1, *h2, *w, *U2, *U3;
    cudaGetSymbolAddress((void**)&h1, g_h1);
    cudaGetSymbolAddress((void**)&h2, g_h2);
    cudaGetSymbolAddress((void**)&w,  g_w);
    cudaGetSymbolAddress((void**)&U2, g_U2);
    cudaGetSymbolAddress((void**)&U3, g_U3);

    static int inited = 0;
    if (!inited) {
        cudaFuncSetAttribute(wino_conv<true>,
            cudaFuncAttributeMaxDynamicSharedMemorySize, SMEM_FLOATS * 4);
        cudaFuncSetAttribute(wino_conv<false>,
            cudaFuncAttributeMaxDynamicSharedMemorySize, SMEM_FLOATS * 4);
        inited = 1;
    }

    // weight transforms (tiny)
    wino_wtrans<<<(64 * 64 + 255) / 256, 256>>>(W2, U2, 64, 64);
    wino_wtrans<<<(169 * 64 + 255) / 256, 256>>>(W3, U3, 169, 64);

    // conv1: 1 -> 64, relu (direct)
    conv3x3_v3<1, 1, true><<<dim3(8, 8, BATCH * 4), dim3(16, 16)>>>(
        x, HW, HW, W1, b1, h1, HW, HW, 0, 64, 4);

    // conv2: 64 -> 64, relu (Winograd)
    wino_conv<true><<<dim3(16, 16, BATCH * 4), 256, SMEM_FLOATS * 4>>>(
        h1, U2, b2, h2, HW, HW, 0, 64, 4);

    // conv3: 64 -> 169 (pad to 176), cropped interior (244x244, +6), no relu
    wino_conv<false><<<dim3(16, 16, BATCH * 11), 256, SMEM_FLOATS * 4>>>(
        h2, U3, b3, w, HO, HO, 6, 169, 11);

    // final per-pixel 13x13 patch dot-product
    int n = BATCH * HO * HO;
    agg_kernel<<<(n + 255) / 256, 256>>>(x, y);
}

// round 6
// speedup vs baseline: 2.0933x; 1.0510x over previous
#include <cuda_runtime.h>

#define BATCH 8
#define HW 256
#define KK 13
#define HO 244   // 256 - 13 + 1

// ---- scratch (__device__ globals; no allocations allowed) ----
static __device__ float g_h1[(size_t)BATCH * 64 * HW * HW];    // conv1 out
static __device__ float g_h2[(size_t)BATCH * 64 * HW * HW];    // conv2 out
static __device__ float g_w [(size_t)BATCH * 169 * HO * HO];   // conv3 out (cropped)
static __device__ float g_U2[(size_t)16 * 64 * 64];            // W2: [xi][cin][oc]
static __device__ float g_U3[(size_t)16 * 64 * 169];           // W3: [xi][cin][oc]

__device__ __forceinline__ unsigned su(const void* p) {
    return (unsigned)__cvta_generic_to_shared(p);
}
__device__ __forceinline__ void cp4(unsigned dst, const void* src, int ok) {
    asm volatile("cp.async.ca.shared.global [%0], [%1], 4, %2;"
                 :: "r"(dst), "l"(src), "r"(ok ? 4 : 0));
}
#define CP_COMMIT() asm volatile("cp.async.commit_group;" ::: "memory")
#define CP_WAIT0()  asm volatile("cp.async.wait_group 0;"  ::: "memory")

// ---------------------------------------------------------------------------
// Weight transform: U = G g G^T for F(2x2,3x3). Gmem layout U[xi][cin][oc].
__global__ void wino_wtrans(const float* __restrict__ Wt, float* __restrict__ U,
                            int OC, int CIN)
{
    int id = blockIdx.x * 256 + threadIdx.x;
    if (id >= OC * CIN) return;
    int oc = id / CIN, c = id % CIN;
    const float* g = Wt + (size_t)id * 9;
    float u[4][3];
#pragma unroll
    for (int j = 0; j < 3; ++j) {
        float g0 = g[j], g1 = g[3 + j], g2 = g[6 + j];
        u[0][j] = g0;
        u[1][j] = 0.5f * (g0 + g1 + g2);
        u[2][j] = 0.5f * (g0 - g1 + g2);
        u[3][j] = g2;
    }
#pragma unroll
    for (int i = 0; i < 4; ++i) {
        float a = u[i][0], b = u[i][1], cc = u[i][2];
        float U4[4] = { a, 0.5f * (a + b + cc), 0.5f * (a - b + cc), cc };
#pragma unroll
        for (int j = 0; j < 4; ++j)
            U[((size_t)(i * 4 + j) * CIN + c) * OC + oc] = U4[j];
    }
}

// ---------------------------------------------------------------------------
// Winograd F(2x2,3x3), CIN=64 in chunks of 8, cp.async double-buffered.
// CTA: 16x16 outputs (8x8 tiles) x 16 oc.
// smem: sIn[2][2592] | sU[2][2560] | sV[8704] (sM aliases sV) = 19008 floats.
#define SMEM_FLOATS 19008

template <bool RELU>
__global__ void __launch_bounds__(256, 2) wino_conv(
    const float* __restrict__ in,
    const float* __restrict__ Ug, const float* __restrict__ bias,
    float* __restrict__ out, int outH, int outW,
    int inOff, int OC, int ocGroups)
{
    extern __shared__ float sm[];
    float* sInBuf[2] = { sm, sm + 2592 };
    float* sUBuf [2] = { sm + 5184, sm + 7744 };
    float* sV = sm + 10304;     // (c*16 + xi)*68 + tile
    float* sM = sV;             // phase C alias: (oc*64 + tile)*17 + xi

    const int tid = threadIdx.x;
    const int xi  = tid & 15;
    const int ocg = (tid >> 4) & 1;
    const int tg  = tid >> 5;

    const int b  = blockIdx.z / ocGroups;
    const int og = blockIdx.z % ocGroups;
    const int ocBase = og * 16;
    const int x0 = blockIdx.x * 16, y0 = blockIdx.y * 16;

    const float* inB = in + (size_t)b * 64 * HW * HW;

    // Hoisted phase-A mapping (2 work-items per thread).
    int paSrc[2], paC16[2], paT[2];
#pragma unroll
    for (int q = 0; q < 2; ++q) {
        int p = tid + 256 * q;
        int c = p >> 6, t = p & 63;
        int ty = t >> 3, tx = t & 7;
        paSrc[q] = c * 324 + ty * 36 + tx * 2;
        paC16[q] = c * 16;
        paT[q]   = t;
    }

    float acc[8][8];
#pragma unroll
    for (int j = 0; j < 8; ++j)
#pragma unroll
        for (int t = 0; t < 8; ++t) acc[j][t] = 0.f;

    // ---- async stage of one channel chunk ----
    auto stage = [&](int c0, float* sInD, float* sUD) {
#pragma unroll
        for (int k = 0; k < 11; ++k) {
            int idx = tid + 256 * k;
            if (idx < 2592) {
                int c  = idx / 324;
                int r  = idx - c * 324;
                int ry = r / 18, rx = r - ry * 18;
                int iy = y0 + inOff + ry - 1;
                int ix = x0 + inOff + rx - 1;
                int ok = (iy >= 0 && iy < HW && ix >= 0 && ix < HW);
                int cy = min(max(iy, 0), HW - 1);
                int cx = min(max(ix, 0), HW - 1);
                cp4(su(sInD + idx),
                    inB + ((size_t)(c0 + c) * HW + cy) * HW + cx, ok);
            }
        }
#pragma unroll
        for (int k = 0; k < 8; ++k) {
            int idx = tid + 256 * k;
            int x  = idx >> 7;
            int r  = idx & 127;
            int c  = r >> 4, oc = r & 15;
            int ocG = ocBase + oc;
            int ok  = (ocG < OC);
            int ocC = ok ? ocG : (OC - 1);
            cp4(su(sUD + (c * 16 + x) * 20 + oc),
                Ug + ((size_t)x * 64 + c0 + c) * OC + ocC, ok);
        }
        CP_COMMIT();
    };

    stage(0, sInBuf[0], sUBuf[0]);

    for (int ci = 0; ci < 8; ++ci) {
        const int cur = ci & 1;
        float* sIn = sInBuf[cur];
        float* sU  = sUBuf[cur];

        CP_WAIT0();
        __syncthreads();
        if (ci < 7) stage((ci + 1) * 8, sInBuf[cur ^ 1], sUBuf[cur ^ 1]);

        // ---- phase A: V = B^T d B -> sV[c][xi][tile] ----
#pragma unroll
        for (int q = 0; q < 2; ++q) {
            const float2* base2 = (const float2*)(sIn + paSrc[q]);
            float d[4][4];
#pragma unroll
            for (int r = 0; r < 4; ++r) {
                float2 lo = base2[r * 9];
                float2 hi = base2[r * 9 + 1];
                d[r][0] = lo.x; d[r][1] = lo.y; d[r][2] = hi.x; d[r][3] = hi.y;
            }
            float z[4][4];
#pragma unroll
            for (int s = 0; s < 4; ++s) {
                z[0][s] = d[0][s] - d[2][s];
                z[1][s] = d[1][s] + d[2][s];
                z[2][s] = d[2][s] - d[1][s];
                z[3][s] = d[1][s] - d[3][s];
            }
#pragma unroll
            for (int i = 0; i < 4; ++i) {
                float* dst = sV + (paC16[q] + i * 4) * 68 + paT[q];
                dst[0]       = z[i][0] - z[i][2];
                dst[68]      = z[i][1] + z[i][2];
                dst[2 * 68]  = z[i][2] - z[i][1];
                dst[3 * 68]  = z[i][1] - z[i][3];
            }
        }
        __syncthreads();

        // ---- phase B: vectorized rank-1 updates per channel ----
#pragma unroll
        for (int c = 0; c < 8; ++c) {
            const float4 v0 = *(const float4*)&sV[(c * 16 + xi) * 68 + tg * 8];
            const float4 v1 = *(const float4*)&sV[(c * 16 + xi) * 68 + tg * 8 + 4];
            const float4 u0 = *(const float4*)&sU[(c * 16 + xi) * 20 + ocg * 8];
            const float4 u1 = *(const float4*)&sU[(c * 16 + xi) * 20 + ocg * 8 + 4];
            float vv[8] = { v0.x, v0.y, v0.z, v0.w, v1.x, v1.y, v1.z, v1.w };
            float uu[8] = { u0.x, u0.y, u0.z, u0.w, u1.x, u1.y, u1.z, u1.w };
#pragma unroll
            for (int j = 0; j < 8; ++j)
#pragma unroll
                for (int t = 0; t < 8; ++t)
                    acc[j][t] = fmaf(uu[j], vv[t], acc[j][t]);
        }
        __syncthreads();
    }

    // ---- phase C: Y = A^T M A, two oc halves via sM ----
#pragma unroll 1
    for (int h = 0; h < 2; ++h) {
        if (ocg == h) {
#pragma unroll
            for (int j = 0; j < 8; ++j)
#pragma unroll
                for (int t = 0; t < 8; ++t)
                    sM[(j * 64 + tg * 8 + t) * 17 + xi] = acc[j][t];
        }
        __syncthreads();
        for (int p = tid; p < 512; p += 256) {
            int oc = p >> 6, t = p & 63;
            int ocG = ocBase + h * 8 + oc;
            if (ocG < OC) {
                const float* src = sM + (oc * 64 + t) * 17;
                float m[4][4];
#pragma unroll
                for (int i = 0; i < 4; ++i)
#pragma unroll
                    for (int j = 0; j < 4; ++j) m[i][j] = src[i * 4 + j];
                float s0[4], s1[4];
#pragma unroll
                for (int j = 0; j < 4; ++j) {
                    s0[j] = m[0][j] + m[1][j] + m[2][j];
                    s1[j] = m[1][j] - m[2][j] - m[3][j];
                }
                float bv = bias[ocG];
                float y00 = s0[0] + s0[1] + s0[2] + bv;
                float y01 = s0[1] - s0[2] - s0[3] + bv;
                float y10 = s1[0] + s1[1] + s1[2] + bv;
                float y11 = s1[1] - s1[2] - s1[3] + bv;
                if (RELU) {
                    y00 = fmaxf(y00, 0.f); y01 = fmaxf(y01, 0.f);
                    y10 = fmaxf(y10, 0.f); y11 = fmaxf(y11, 0.f);
                }
                int oy = y0 + (t >> 3) * 2;
                int ox = x0 + (t & 7) * 2;
                float* o0 = out + ((size_t)((size_t)b * OC + ocG)
                                   * outH + oy) * outW + ox;
                if (oy < outH) {
                    if (ox     < outW) o0[0] = y00;
                    if (ox + 1 < outW) o0[1] = y01;
                }
                if (oy + 1 < outH) {
                    if (ox     < outW) o0[outW]     = y10;
                    if (ox + 1 < outW) o0[outW + 1] = y11;
                }
            }
        }
        __syncthreads();
    }
}

// ---------------------------------------------------------------------------
// conv1 (1 -> 64): direct, register-tiled (cheap layer).
template <int CIN, int CC, bool RELU>
__global__ void __launch_bounds__(256) conv3x3_v3(
    const float* __restrict__ in, int inH, int inW,
    const float* __restrict__ Wt, const float* __restrict__ bias,
    float* __restrict__ out, int outH, int outW,
    int inOff, int OC, int ocGroups)
{
    __shared__ float sIn[CC][34][34];
    __shared__ float sW[16][CC][9];

    const int tx = threadIdx.x, ty = threadIdx.y;
    const int tid = ty * 16 + tx;
    const int b  = blockIdx.z / ocGroups;
    const int og = blockIdx.z % ocGroups;
    const int ocBase = og * 16;
    const int x0 = blockIdx.x * 32, y0 = blockIdx.y * 32;

    float acc[16][4];
#pragma unroll
    for (int o = 0; o < 16; ++o)
#pragma unroll
        for (int p = 0; p < 4; ++p) acc[o][p] = 0.f;

    const float* inB = in + (size_t)b * CIN * inH * inW;

    for (int c0 = 0; c0 < CIN; c0 += CC) {
        for (int idx = tid; idx < CC * 34 * 34; idx += 256) {
            int c  = idx / (34 * 34);
            int r  = idx % (34 * 34);
            int ry = r / 34, rx = r % 34;
            int iy = y0 + inOff + ry - 1;
            int ix = x0 + inOff + rx - 1;
            float v = 0.f;
            if (iy >= 0 && iy < inH && ix >= 0 && ix < inW)
                v = inB[((size_t)(c0 + c) * inH + iy) * inW + ix];
            sIn[c][ry][rx] = v;
        }
        for (int idx = tid; idx < 16 * CC * 9; idx += 256) {
            int o = idx / (CC * 9);
            int r = idx % (CC * 9);
            int c = r / 9, t = r % 9;
            int oc = ocBase + o;
            sW[o][c][t] = (oc < OC)
                ? Wt[((size_t)oc * CIN + (c0 + c)) * 9 + t] : 0.f;
        }
        __syncthreads();

#pragma unroll 1
        for (int c = 0; c < CC; ++c) {
            float v[4][4];
#pragma unroll
            for (int u = 0; u < 4; ++u)
#pragma unroll
                for (int w = 0; w < 4; ++w)
                    v[u][w] = sIn[c][2 * ty + u][2 * tx + w];
#pragma unroll
            for (int o = 0; o < 16; ++o) {
#pragma unroll
                for (int ky = 0; ky < 3; ++ky) {
#pragma unroll
                    for (int kx = 0; kx < 3; ++kx) {
                        float wv = sW[o][c][ky * 3 + kx];
                        acc[o][0] = fmaf(v[ky    ][kx    ], wv, acc[o][0]);
                        acc[o][1] = fmaf(v[ky    ][kx + 1], wv, acc[o][1]);
                        acc[o][2] = fmaf(v[ky + 1][kx    ], wv, acc[o][2]);
                        acc[o][3] = fmaf(v[ky + 1][kx + 1], wv, acc[o][3]);
                    }
                }
            }
        }
        __syncthreads();
    }

    const int ox = x0 + 2 * tx;
#pragma unroll
    for (int o = 0; o < 16; ++o) {
        int oc = ocBase + o;
        if (oc >= OC) continue;
        float bv = bias[oc];
#pragma unroll
        for (int py = 0; py < 2; ++py) {
            int oy = y0 + 2 * ty + py;
            if (oy >= outH || ox >= outW) continue;
            float r0 = acc[o][2 * py    ] + bv;
            float r1 = acc[o][2 * py + 1] + bv;
            if (RELU) { r0 = fmaxf(r0, 0.f); r1 = fmaxf(r1, 0.f); }
            *(float2*)&out[((size_t)((size_t)b * OC + oc) * outH + oy) * outW + ox]
                = make_float2(r0, r1);
        }
    }
}

// y[b,i,j] = sum_{u,v} x[b, i+u, j+v] * w[b, u*13+v, i, j]
__global__ void __launch_bounds__(256) agg_kernel(
    const float* __restrict__ x, float* __restrict__ y)
{
    int id = blockIdx.x * 256 + threadIdx.x;
    if (id >= BATCH * HO * HO) return;
    int j = id % HO;
    int i = (id / HO) % HO;
    int b = id / (HO * HO);
    const float* xb = x + (size_t)b * HW * HW;
    const float* wb = g_w + (size_t)b * 169 * HO * HO + (size_t)i * HO + j;
    float acc = 0.f;
    for (int u = 0; u < KK; ++u) {
        const float* xr = xb + (size_t)(i + u) * HW + j;
#pragma unroll
        for (int v = 0; v < KK; ++v)
            acc = fmaf(xr[v], wb[(size_t)(u * KK + v) * HO * HO], acc);
    }
    y[id] = acc;
}

extern "C" void kernel_launch(void* const* d_in, const int* in_sizes, int n_in,
                              void* d_out, int out_size)
{
    const float* x  = (const float*)d_in[0];
    const float* W1 = (const float*)d_in[1];
    const float* b1 = (const float*)d_in[2];
    const float* W2 = (const float*)d_in[3];
    const float* b2 = (const float*)d_in[4];
    const float* W3 = (const float*)d_in[5];
    const float* b3 = (const float*)d_in[6];
    float* y = (float*)d_out;

    float *h1, *h2, *w, *U2, *U3;
    cudaGetSymbolAddress((void**)&h1, g_h1);
    cudaGetSymbolAddress((void**)&h2, g_h2);
    cudaGetSymbolAddress((void**)&w,  g_w);
    cudaGetSymbolAddress((void**)&U2, g_U2);
    cudaGetSymbolAddress((void**)&U3, g_U3);

    static int inited = 0;
    if (!inited) {
        cudaFuncSetAttribute(wino_conv<true>,
            cudaFuncAttributeMaxDynamicSharedMemorySize, SMEM_FLOATS * 4);
        cudaFuncSetAttribute(wino_conv<false>,
            cudaFuncAttributeMaxDynamicSharedMemorySize, SMEM_FLOATS * 4);
        inited = 1;
    }

    // weight transforms (tiny)
    wino_wtrans<<<(64 * 64 + 255) / 256, 256>>>(W2, U2, 64, 64);
    wino_wtrans<<<(169 * 64 + 255) / 256, 256>>>(W3, U3, 169, 64);

    // conv1: 1 -> 64, relu (direct)
    conv3x3_v3<1, 1, true><<<dim3(8, 8, BATCH * 4), dim3(16, 16)>>>(
        x, HW, HW, W1, b1, h1, HW, HW, 0, 64, 4);

    // conv2: 64 -> 64, relu (Winograd)
    wino_conv<true><<<dim3(16, 16, BATCH * 4), 256, SMEM_FLOATS * 4>>>(
        h1, U2, b2, h2, HW, HW, 0, 64, 4);

    // conv3: 64 -> 169 (pad to 176), cropped interior (244x244, +6), no relu
    wino_conv<false><<<dim3(16, 16, BATCH * 11), 256, SMEM_FLOATS * 4>>>(
        h2, U3, b3, w, HO, HO, 6, 169, 11);

    // final per-pixel 13x13 patch dot-product
    int n = BATCH * HO * HO;
    agg_kernel<<<(n + 255) / 256, 256>>>(x, y);
}